// round 3
// baseline (speedup 1.0000x reference)
#include <cuda_runtime.h>
#include <math.h>

#define Bn 4
#define Pp 4
#define Cc 64
#define NH 8
#define DH 8
#define Hh 128
#define Wd 128
#define HW 16384
#define TOK 32

// scratch (no cudaMalloc allowed)
__device__ float g_mb[16 * HW];     // [(b*4+p)][pos] mask-bias per polarization

// ---------------------------------------------------------------------------
// packed f32x2 helpers (SASS FFMA2 path — ptxas won't emit this from C++)
// ---------------------------------------------------------------------------
__device__ __forceinline__ unsigned long long fma2(unsigned long long a,
                                                   unsigned long long b,
                                                   unsigned long long c) {
    unsigned long long d;
    asm("fma.rn.f32x2 %0, %1, %2, %3;" : "=l"(d) : "l"(a), "l"(b), "l"(c));
    return d;
}
__device__ __forceinline__ unsigned long long mul2(unsigned long long a,
                                                   unsigned long long b) {
    unsigned long long d;
    asm("mul.rn.f32x2 %0, %1, %2;" : "=l"(d) : "l"(a), "l"(b));
    return d;
}
__device__ __forceinline__ unsigned long long pack2(float lo, float hi) {
    unsigned long long d;
    asm("mov.b64 %0, {%1, %2};" : "=l"(d) : "f"(lo), "f"(hi));
    return d;
}
__device__ __forceinline__ void unpack2(unsigned long long v, float& lo, float& hi) {
    asm("mov.b64 {%0, %1}, %2;" : "=f"(lo), "=f"(hi) : "l"(v));
}

// ---------------------------------------------------------------------------
// Kernel 1: mask branch. wbar folded in (recomputed per block — trivial).
// depthwise 3x3 (SAME) -> exact GELU -> dot wbar -> g_mb
// ---------------------------------------------------------------------------
__global__ void mask_kernel2(const float* __restrict__ mask,
                             const float* __restrict__ dw_w,
                             const float* __restrict__ dw_b,
                             const float* __restrict__ pw_w,
                             const float* __restrict__ pw_b) {
    __shared__ float tile[18][20];
    __shared__ float sdw[Cc][9];
    __shared__ float sdb[Cc];
    __shared__ float swbar[Cc + 1];

    int bp = blockIdx.z;
    int h0 = blockIdx.y * 16, w0 = blockIdx.x * 16;
    int tx = threadIdx.x, ty = threadIdx.y;
    int tid = ty * 16 + tx;

    for (int i = tid; i < Cc * 9; i += 256) sdw[i / 9][i % 9] = dw_w[i];
    for (int i = tid; i < Cc; i += 256) sdb[i] = dw_b[i];
    if (tid < Cc) {
        float s = 0.f;
        for (int d = 0; d < Cc; ++d) s += pw_w[d * Cc + tid];
        swbar[tid] = s * (1.0f / Cc);
    }
    if (tid == 0) {
        float sb = 0.f;
        for (int d = 0; d < Cc; ++d) sb += pw_b[d];
        swbar[Cc] = sb * (1.0f / Cc);
    }

    float acc = 0.f;
    const float* base = mask + (size_t)bp * Cc * HW;

    for (int c = 0; c < Cc; ++c) {
        __syncthreads();
        for (int i = tid; i < 18 * 18; i += 256) {
            int hy = i / 18, wx = i % 18;
            int gh = h0 + hy - 1, gw = w0 + wx - 1;
            float v = 0.f;
            if (gh >= 0 && gh < Hh && gw >= 0 && gw < Wd)
                v = base[(size_t)c * HW + gh * Wd + gw];
            tile[hy][wx] = v;
        }
        __syncthreads();
        float y = sdb[c];
#pragma unroll
        for (int dy = 0; dy < 3; ++dy)
#pragma unroll
            for (int dx = 0; dx < 3; ++dx)
                y += tile[ty + dy][tx + dx] * sdw[c][dy * 3 + dx];
        float g = 0.5f * y * (1.0f + erff(y * 0.70710678118654752f));
        acc += swbar[c] * g;
    }
    acc += swbar[Cc];
    g_mb[(size_t)bp * HW + (h0 + ty) * Wd + (w0 + tx)] = acc;
}

// ---------------------------------------------------------------------------
// Kernel 2: fused QK + normalize + 4x4 softmax + fused AV + projection.
// Entire arithmetic in packed f32x2; q/k never unpacked (no spill pressure).
// block = 256 threads = 32 tokens x 8 heads; 2 blocks/SM.
// smem (floats):
//   sW   [4][64][64]  0        (transposed [c][d])  wq,wk,wv,wproj
//   x_s  [64][32][4]  16384    (aliased: o_s, then out staging [256][32])
//   mb_s [32][4]      24576
//   sb   [64]         24704
//   sr   [8]          24768
// total = 24776 floats = 99104 B  -> 2 blocks/SM
// ---------------------------------------------------------------------------
#define SMEM_FLOATS 24776

__global__ void __launch_bounds__(256, 2)
attn_kernel(const float* __restrict__ x_in,
            const float* __restrict__ wq,
            const float* __restrict__ wk,
            const float* __restrict__ wv,
            const float* __restrict__ wp,
            const float* __restrict__ b_proj,
            const float* __restrict__ rescale,
            float* __restrict__ out) {
    extern __shared__ float sm[];
    float* sW   = sm;
    float* x_s  = sm + 16384;   // aliased o_s / out_s
    float* mb_s = sm + 24576;
    float* sb   = sm + 24704;
    float* sr   = sm + 24768;

    int tid = threadIdx.x;
    int b = blockIdx.y;
    int pos0 = blockIdx.x * TOK;

    // --- stage weights transposed [c][d]; float4 global reads ---
    const float* Ws[4] = {wq, wk, wv, wp};
#pragma unroll
    for (int m = 0; m < 4; ++m) {
        for (int i4 = tid; i4 < 1024; i4 += 256) {
            int d = i4 >> 4, c4 = (i4 & 15) * 4;
            float4 w4 = *(const float4*)(Ws[m] + d * 64 + c4);
            float* dst = sW + m * 4096 + c4 * 64 + d;
            dst[0] = w4.x; dst[64] = w4.y; dst[128] = w4.z; dst[192] = w4.w;
        }
    }
    // --- stage x as x_s[c][t][p]; float4 global reads ---
    for (int i4 = tid; i4 < 2048; i4 += 256) {
        int pc = i4 >> 3;              // p*64+c
        int t4 = (i4 & 7) * 4;
        int p = pc >> 6, c = pc & 63;
        float4 xv = *(const float4*)(x_in + (size_t)((b * 4 + p) * 64 + c) * HW + pos0 + t4);
        float* dst = x_s + c * 128 + t4 * 4 + p;
        dst[0] = xv.x; dst[4] = xv.y; dst[8] = xv.z; dst[12] = xv.w;
    }
    if (tid < 128) {
        int p = tid >> 5, t = tid & 31;
        mb_s[t * 4 + p] = g_mb[(size_t)(b * 4 + p) * HW + pos0 + t];
    }
    if (tid < 64) sb[tid] = b_proj[tid];
    if (tid < 8) sr[tid] = rescale[tid];
    __syncthreads();

    const int t = tid >> 3;    // token in tile
    const int h = tid & 7;     // head

    const float* wqb = sW + h * 8;
    const float* wkb = sW + 4096 + h * 8;
    const float* wvb = sW + 8192 + h * 8;
    const float* wpb = sW + 12288 + h * 8;

    // ===== phase 1: Q,K GEMM (packed j-pairs), packed accumulators =====
    unsigned long long qa[4][4], ka[4][4];
#pragma unroll
    for (int p = 0; p < 4; ++p)
#pragma unroll
        for (int i = 0; i < 4; ++i) { qa[p][i] = 0ULL; ka[p][i] = 0ULL; }

#pragma unroll 2
    for (int c = 0; c < 64; ++c) {
        float4 xv = *(const float4*)(x_s + c * 128 + t * 4);
        ulonglong2 wq0 = *(const ulonglong2*)(wqb + c * 64);
        ulonglong2 wq1 = *(const ulonglong2*)(wqb + c * 64 + 4);
        ulonglong2 wk0 = *(const ulonglong2*)(wkb + c * 64);
        ulonglong2 wk1 = *(const ulonglong2*)(wkb + c * 64 + 4);
        float xr[4] = {xv.x, xv.y, xv.z, xv.w};
#pragma unroll
        for (int p = 0; p < 4; ++p) {
            unsigned long long xp2 = pack2(xr[p], xr[p]);
            qa[p][0] = fma2(xp2, wq0.x, qa[p][0]);
            qa[p][1] = fma2(xp2, wq0.y, qa[p][1]);
            qa[p][2] = fma2(xp2, wq1.x, qa[p][2]);
            qa[p][3] = fma2(xp2, wq1.y, qa[p][3]);
            ka[p][0] = fma2(xp2, wk0.x, ka[p][0]);
            ka[p][1] = fma2(xp2, wk0.y, ka[p][1]);
            ka[p][2] = fma2(xp2, wk1.x, ka[p][2]);
            ka[p][3] = fma2(xp2, wk1.y, ka[p][3]);
        }
    }

    // ===== L2 normalize (stay packed) =====
#pragma unroll
    for (int p = 0; p < 4; ++p) {
        unsigned long long s2q = 0ULL, s2k = 0ULL;
#pragma unroll
        for (int i = 0; i < 4; ++i) {
            s2q = fma2(qa[p][i], qa[p][i], s2q);
            s2k = fma2(ka[p][i], ka[p][i], s2k);
        }
        float qlo, qhi, klo, khi;
        unpack2(s2q, qlo, qhi);
        unpack2(s2k, klo, khi);
        float iq = 1.0f / fmaxf(sqrtf(qlo + qhi), 1e-12f);
        float ik = 1.0f / fmaxf(sqrtf(klo + khi), 1e-12f);
        unsigned long long iq2 = pack2(iq, iq);
        unsigned long long ik2 = pack2(ik, ik);
#pragma unroll
        for (int i = 0; i < 4; ++i) {
            qa[p][i] = mul2(qa[p][i], iq2);
            ka[p][i] = mul2(ka[p][i], ik2);
        }
    }

    float mbl[4];
#pragma unroll
    for (int p = 0; p < 4; ++p) mbl[p] = mb_s[t * 4 + p];
    float rh = sr[h];

    // ===== attention scores (packed dots) + softmax =====
    float att[4][4];
#pragma unroll
    for (int p = 0; p < 4; ++p) {
#pragma unroll
        for (int pq = 0; pq < 4; ++pq) {
            unsigned long long d2 = 0ULL;
#pragma unroll
            for (int i = 0; i < 4; ++i) d2 = fma2(qa[p][i], ka[pq][i], d2);
            float lo, hi;
            unpack2(d2, lo, hi);
            att[p][pq] = (lo + hi) * rh + (mbl[pq] - mbl[p]);
        }
        float mx = fmaxf(fmaxf(att[p][0], att[p][1]), fmaxf(att[p][2], att[p][3]));
        float s = 0.f;
#pragma unroll
        for (int pq = 0; pq < 4; ++pq) { att[p][pq] = __expf(att[p][pq] - mx); s += att[p][pq]; }
        float inv = 1.0f / s;
#pragma unroll
        for (int pq = 0; pq < 4; ++pq) att[p][pq] *= inv;
    }

    // ===== phase 2: fused AV: o[p][j] = sum_c (sum_pq att[p][pq] x[pq][c]) wv[c][j]
    unsigned long long oa[4][4];
#pragma unroll
    for (int p = 0; p < 4; ++p)
#pragma unroll
        for (int i = 0; i < 4; ++i) oa[p][i] = 0ULL;

#pragma unroll 2
    for (int c = 0; c < 64; ++c) {
        float4 xv = *(const float4*)(x_s + c * 128 + t * 4);
        ulonglong2 wv0 = *(const ulonglong2*)(wvb + c * 64);
        ulonglong2 wv1 = *(const ulonglong2*)(wvb + c * 64 + 4);
#pragma unroll
        for (int p = 0; p < 4; ++p) {
            float y = att[p][0] * xv.x + att[p][1] * xv.y +
                      att[p][2] * xv.z + att[p][3] * xv.w;
            unsigned long long y2 = pack2(y, y);
            oa[p][0] = fma2(y2, wv0.x, oa[p][0]);
            oa[p][1] = fma2(y2, wv0.y, oa[p][1]);
            oa[p][2] = fma2(y2, wv1.x, oa[p][2]);
            oa[p][3] = fma2(y2, wv1.y, oa[p][3]);
        }
    }

    // x_s becomes o_s — wait for all readers of x_s first
    __syncthreads();
#pragma unroll
    for (int p = 0; p < 4; ++p)
#pragma unroll
        for (int i = 0; i < 4; ++i) {
            float lo, hi;
            unpack2(oa[p][i], lo, hi);
            x_s[(h * 8 + 2 * i) * 128 + t * 4 + p] = lo;
            x_s[(h * 8 + 2 * i + 1) * 128 + t * 4 + p] = hi;
        }
    __syncthreads();

    // ===== phase 3: projection (packed) =====
    unsigned long long acc[4][4];
    {
        ulonglong2 b0 = *(const ulonglong2*)(sb + h * 8);
        ulonglong2 b1 = *(const ulonglong2*)(sb + h * 8 + 4);
#pragma unroll
        for (int p = 0; p < 4; ++p) {
            acc[p][0] = b0.x; acc[p][1] = b0.y; acc[p][2] = b1.x; acc[p][3] = b1.y;
        }
    }
#pragma unroll 2
    for (int c = 0; c < 64; ++c) {
        float4 ov = *(const float4*)(x_s + c * 128 + t * 4);
        ulonglong2 w0 = *(const ulonglong2*)(wpb + c * 64);
        ulonglong2 w1 = *(const ulonglong2*)(wpb + c * 64 + 4);
        float orr[4] = {ov.x, ov.y, ov.z, ov.w};
#pragma unroll
        for (int p = 0; p < 4; ++p) {
            unsigned long long o2 = pack2(orr[p], orr[p]);
            acc[p][0] = fma2(o2, w0.x, acc[p][0]);
            acc[p][1] = fma2(o2, w0.y, acc[p][1]);
            acc[p][2] = fma2(o2, w1.x, acc[p][2]);
            acc[p][3] = fma2(o2, w1.y, acc[p][3]);
        }
    }

    // stage to out_s[(p*64+c)][t] (x_s region, o dead after proj loop)
    __syncthreads();
#pragma unroll
    for (int p = 0; p < 4; ++p)
#pragma unroll
        for (int i = 0; i < 4; ++i) {
            float lo, hi;
            unpack2(acc[p][i], lo, hi);
            x_s[(p * 64 + h * 8 + 2 * i) * 32 + t] = lo;
            x_s[(p * 64 + h * 8 + 2 * i + 1) * 32 + t] = hi;
        }
    __syncthreads();

    // coalesced float4 writeback
    for (int i4 = tid; i4 < 2048; i4 += 256) {
        int pc = i4 >> 3;
        int tq = (i4 & 7) * 4;
        int p = pc >> 6, c = pc & 63;
        float4 v = *(const float4*)(x_s + pc * 32 + tq);
        *(float4*)(out + (size_t)((b * 4 + p) * 64 + c) * HW + pos0 + tq) = v;
    }
}

// ---------------------------------------------------------------------------
extern "C" void kernel_launch(void* const* d_in, const int* in_sizes, int n_in,
                              void* d_out, int out_size) {
    (void)in_sizes; (void)n_in; (void)out_size;
    const float* x_in   = (const float*)d_in[0];
    const float* mask   = (const float*)d_in[1];
    const float* wq     = (const float*)d_in[2];
    const float* wk     = (const float*)d_in[3];
    const float* wv     = (const float*)d_in[4];
    const float* w_proj = (const float*)d_in[5];
    const float* b_proj = (const float*)d_in[6];
    const float* rescale= (const float*)d_in[7];
    const float* dw_w   = (const float*)d_in[8];
    const float* dw_b   = (const float*)d_in[9];
    const float* pw_w   = (const float*)d_in[10];
    const float* pw_b   = (const float*)d_in[11];
    float* out = (float*)d_out;

    cudaFuncSetAttribute(attn_kernel,
                         cudaFuncAttributeMaxDynamicSharedMemorySize,
                         SMEM_FLOATS * sizeof(float));

    mask_kernel2<<<dim3(8, 8, 16), dim3(16, 16)>>>(mask, dw_w, dw_b, pw_w, pw_b);
    attn_kernel<<<dim3(HW / TOK, Bn), 256, SMEM_FLOATS * sizeof(float)>>>(
        x_in, wq, wk, wv, w_proj, b_proj, rescale, out);
}

// round 4
// speedup vs baseline: 1.8802x; 1.8802x over previous
#include <cuda_runtime.h>
#include <math.h>

#define Bn 4
#define Pp 4
#define Cc 64
#define NH 8
#define DH 8
#define Hh 128
#define Wd 128
#define HW 16384
#define TOK 64

// scratch (no cudaMalloc allowed)
__device__ float g_mb[16 * HW];     // [(b*4+p)][pos] mask-bias per polarization

// ---------------------------------------------------------------------------
// packed f32x2 helpers
// ---------------------------------------------------------------------------
__device__ __forceinline__ unsigned long long fma2(unsigned long long a,
                                                   unsigned long long b,
                                                   unsigned long long c) {
    unsigned long long d;
    asm("fma.rn.f32x2 %0, %1, %2, %3;" : "=l"(d) : "l"(a), "l"(b), "l"(c));
    return d;
}
__device__ __forceinline__ unsigned long long mul2(unsigned long long a,
                                                   unsigned long long b) {
    unsigned long long d;
    asm("mul.rn.f32x2 %0, %1, %2;" : "=l"(d) : "l"(a), "l"(b));
    return d;
}
__device__ __forceinline__ unsigned long long pack2(float lo, float hi) {
    unsigned long long d;
    asm("mov.b64 %0, {%1, %2};" : "=l"(d) : "f"(lo), "f"(hi));
    return d;
}
__device__ __forceinline__ void unpack2(unsigned long long v, float& lo, float& hi) {
    asm("mov.b64 {%0, %1}, %2;" : "=f"(lo), "=f"(hi) : "l"(v));
}

// ---------------------------------------------------------------------------
// Kernel 1: mask branch. depthwise 3x3 (SAME) -> exact GELU -> dot wbar.
// wbar computed IN PARALLEL per block (256 threads x 16 partials; warp-reduce
// for the bias) — the R3 serial version cost ~140us, this costs ~5us total.
// ---------------------------------------------------------------------------
__global__ void mask_kernel2(const float* __restrict__ mask,
                             const float* __restrict__ dw_w,
                             const float* __restrict__ dw_b,
                             const float* __restrict__ pw_w,
                             const float* __restrict__ pw_b) {
    __shared__ float tile[18][20];
    __shared__ float sdw[Cc][9];
    __shared__ float sdb[Cc];
    __shared__ float swbar[Cc + 1];
    __shared__ float wpart[4][Cc];

    int bp = blockIdx.z;
    int h0 = blockIdx.y * 16, w0 = blockIdx.x * 16;
    int tx = threadIdx.x, ty = threadIdx.y;
    int tid = ty * 16 + tx;

    for (int i = tid; i < Cc * 9; i += 256) sdw[i / 9][i % 9] = dw_w[i];
    for (int i = tid; i < Cc; i += 256) sdb[i] = dw_b[i];
    // parallel column-mean of pw_w
    {
        int c = tid & 63, dg = tid >> 6;
        float s = 0.f;
        for (int d = dg * 16; d < dg * 16 + 16; ++d) s += pw_w[d * Cc + c];
        wpart[dg][c] = s;
    }
    // bias mean via one warp
    if (tid >= 192) {
        float s = pw_b[tid - 192];
#pragma unroll
        for (int o = 16; o > 0; o >>= 1)
            s += __shfl_down_sync(0xFFFFFFFFu, s, o);
        if (tid == 192) swbar[Cc] = s * (1.0f / Cc);
    }
    __syncthreads();
    if (tid < Cc)
        swbar[tid] = (wpart[0][tid] + wpart[1][tid] + wpart[2][tid] + wpart[3][tid]) * (1.0f / Cc);

    float acc = 0.f;
    const float* base = mask + (size_t)bp * Cc * HW;

    for (int c = 0; c < Cc; ++c) {
        __syncthreads();
        for (int i = tid; i < 18 * 18; i += 256) {
            int hy = i / 18, wx = i % 18;
            int gh = h0 + hy - 1, gw = w0 + wx - 1;
            float v = 0.f;
            if (gh >= 0 && gh < Hh && gw >= 0 && gw < Wd)
                v = base[(size_t)c * HW + gh * Wd + gw];
            tile[hy][wx] = v;
        }
        __syncthreads();
        float y = sdb[c];
#pragma unroll
        for (int dy = 0; dy < 3; ++dy)
#pragma unroll
            for (int dx = 0; dx < 3; ++dx)
                y += tile[ty + dy][tx + dx] * sdw[c][dy * 3 + dx];
        float g = 0.5f * y * (1.0f + erff(y * 0.70710678118654752f));
        acc += swbar[c] * g;
    }
    acc += swbar[Cc];
    g_mb[(size_t)bp * HW + (h0 + ty) * Wd + (w0 + tx)] = acc;
}

// ---------------------------------------------------------------------------
// Kernel 2: 64 tokens/block, 2 adjacent tokens per thread.
// Weight rows bank-swizzled: the two 16B j-groups of head h are swapped for
// h>=4, so the 8 head addresses in a quarter-warp hit all 32 banks.
// smem (floats):
//   sW   [4][64][64]   0       (rows swizzled as above)
//   x_s  [64][64][4]   16384   (aliased: o_s [64][64][4], out_s [256][64])
//   mb_s [64][4]       32768
//   sb   [64]          33024
//   sr   [8]           33088
// total = 33096 floats = 132384 B  -> 1 block/SM, 8 warps
// ---------------------------------------------------------------------------
#define SMEM_FLOATS 33096

__global__ void __launch_bounds__(256, 1)
attn_kernel(const float* __restrict__ x_in,
            const float* __restrict__ wq,
            const float* __restrict__ wk,
            const float* __restrict__ wv,
            const float* __restrict__ wp,
            const float* __restrict__ b_proj,
            const float* __restrict__ rescale,
            float* __restrict__ out) {
    extern __shared__ float sm[];
    float* sW   = sm;
    float* x_s  = sm + 16384;   // aliased o_s / out_s
    float* mb_s = sm + 32768;
    float* sb   = sm + 33024;
    float* sr   = sm + 33088;

    int tid = threadIdx.x;
    int b = blockIdx.y;
    int pos0 = blockIdx.x * TOK;

    // --- stage weights, swizzled: element (d,c) goes to row c, pos(d) ---
    const float* Ws[4] = {wq, wk, wv, wp};
#pragma unroll
    for (int m = 0; m < 4; ++m) {
        for (int i4 = tid; i4 < 1024; i4 += 256) {
            int d = i4 >> 4, c4 = (i4 & 15) * 4;
            float4 w4 = *(const float4*)(Ws[m] + d * 64 + c4);
            int hq = d >> 3;
            int grp = (d >> 2) & 1;
            int gsw = (hq >= 4) ? (1 - grp) : grp;
            int pos = hq * 8 + gsw * 4 + (d & 3);
            float* dst = sW + m * 4096 + c4 * 64 + pos;
            dst[0] = w4.x; dst[64] = w4.y; dst[128] = w4.z; dst[192] = w4.w;
        }
    }
    // --- stage x as x_s[c][t][p] (64 tokens) ---
    for (int i4 = tid; i4 < 4096; i4 += 256) {
        int pc = i4 >> 4;              // p*64+c
        int t4 = (i4 & 15) * 4;
        int p = pc >> 6, c = pc & 63;
        float4 xv = *(const float4*)(x_in + (size_t)((b * 4 + p) * 64 + c) * HW + pos0 + t4);
        float* dst = x_s + c * 256 + t4 * 4 + p;
        dst[0] = xv.x; dst[4] = xv.y; dst[8] = xv.z; dst[12] = xv.w;
    }
    {
        int p = tid >> 6, t = tid & 63;
        mb_s[t * 4 + p] = g_mb[(size_t)(b * 4 + p) * HW + pos0 + t];
    }
    if (tid < 64) sb[tid] = b_proj[tid];
    if (tid < 8) sr[tid] = rescale[tid];
    __syncthreads();

    const int h = tid & 7;
    const int tp = tid >> 3;
    const int t0 = tp * 2;
    const int lo_off = h * 8 + ((h & 4) ? 4 : 0);
    const int hi_off = h * 8 + ((h & 4) ? 0 : 4);

    // ===== phase 1: Q,K for 2 tokens =====
    unsigned long long qa[2][4][4], ka[2][4][4];
#pragma unroll
    for (int tk = 0; tk < 2; ++tk)
#pragma unroll
        for (int p = 0; p < 4; ++p)
#pragma unroll
            for (int i = 0; i < 4; ++i) { qa[tk][p][i] = 0ULL; ka[tk][p][i] = 0ULL; }

#pragma unroll 1
    for (int c = 0; c < 64; ++c) {
        const float* xrow = x_s + c * 256 + t0 * 4;
        float4 xA = *(const float4*)(xrow);
        float4 xB = *(const float4*)(xrow + 4);
        const float* qrow = sW + c * 64;
        const float* krow = sW + 4096 + c * 64;
        ulonglong2 q_lo = *(const ulonglong2*)(qrow + lo_off);
        ulonglong2 q_hi = *(const ulonglong2*)(qrow + hi_off);
        ulonglong2 k_lo = *(const ulonglong2*)(krow + lo_off);
        ulonglong2 k_hi = *(const ulonglong2*)(krow + hi_off);
        float xr[2][4] = {{xA.x, xA.y, xA.z, xA.w}, {xB.x, xB.y, xB.z, xB.w}};
#pragma unroll
        for (int tk = 0; tk < 2; ++tk)
#pragma unroll
            for (int p = 0; p < 4; ++p) {
                unsigned long long xp2 = pack2(xr[tk][p], xr[tk][p]);
                qa[tk][p][0] = fma2(xp2, q_lo.x, qa[tk][p][0]);
                qa[tk][p][1] = fma2(xp2, q_lo.y, qa[tk][p][1]);
                qa[tk][p][2] = fma2(xp2, q_hi.x, qa[tk][p][2]);
                qa[tk][p][3] = fma2(xp2, q_hi.y, qa[tk][p][3]);
                ka[tk][p][0] = fma2(xp2, k_lo.x, ka[tk][p][0]);
                ka[tk][p][1] = fma2(xp2, k_lo.y, ka[tk][p][1]);
                ka[tk][p][2] = fma2(xp2, k_hi.x, ka[tk][p][2]);
                ka[tk][p][3] = fma2(xp2, k_hi.y, ka[tk][p][3]);
            }
    }

    // ===== normalize + scores + softmax (packed) =====
    float att[2][4][4];
    float rh = sr[h];
#pragma unroll
    for (int tk = 0; tk < 2; ++tk) {
#pragma unroll
        for (int p = 0; p < 4; ++p) {
            unsigned long long s2q = 0ULL, s2k = 0ULL;
#pragma unroll
            for (int i = 0; i < 4; ++i) {
                s2q = fma2(qa[tk][p][i], qa[tk][p][i], s2q);
                s2k = fma2(ka[tk][p][i], ka[tk][p][i], s2k);
            }
            float qlo, qhi, klo, khi;
            unpack2(s2q, qlo, qhi);
            unpack2(s2k, klo, khi);
            float iq = 1.0f / fmaxf(sqrtf(qlo + qhi), 1e-12f);
            float ik = 1.0f / fmaxf(sqrtf(klo + khi), 1e-12f);
            unsigned long long iq2 = pack2(iq, iq);
            unsigned long long ik2 = pack2(ik, ik);
#pragma unroll
            for (int i = 0; i < 4; ++i) {
                qa[tk][p][i] = mul2(qa[tk][p][i], iq2);
                ka[tk][p][i] = mul2(ka[tk][p][i], ik2);
            }
        }
        float mbl[4];
#pragma unroll
        for (int p = 0; p < 4; ++p) mbl[p] = mb_s[(t0 + tk) * 4 + p];
#pragma unroll
        for (int p = 0; p < 4; ++p) {
#pragma unroll
            for (int pq = 0; pq < 4; ++pq) {
                unsigned long long d2 = 0ULL;
#pragma unroll
                for (int i = 0; i < 4; ++i) d2 = fma2(qa[tk][p][i], ka[tk][pq][i], d2);
                float lo, hi;
                unpack2(d2, lo, hi);
                att[tk][p][pq] = (lo + hi) * rh + (mbl[pq] - mbl[p]);
            }
            float mx = fmaxf(fmaxf(att[tk][p][0], att[tk][p][1]),
                             fmaxf(att[tk][p][2], att[tk][p][3]));
            float s = 0.f;
#pragma unroll
            for (int pq = 0; pq < 4; ++pq) {
                att[tk][p][pq] = __expf(att[tk][p][pq] - mx);
                s += att[tk][p][pq];
            }
            float inv = 1.0f / s;
#pragma unroll
            for (int pq = 0; pq < 4; ++pq) att[tk][p][pq] *= inv;
        }
    }

    // ===== phase 2: fused AV =====
    unsigned long long oa[2][4][4];
#pragma unroll
    for (int tk = 0; tk < 2; ++tk)
#pragma unroll
        for (int p = 0; p < 4; ++p)
#pragma unroll
            for (int i = 0; i < 4; ++i) oa[tk][p][i] = 0ULL;

#pragma unroll 1
    for (int c = 0; c < 64; ++c) {
        const float* xrow = x_s + c * 256 + t0 * 4;
        float4 xA = *(const float4*)(xrow);
        float4 xB = *(const float4*)(xrow + 4);
        const float* vrow = sW + 8192 + c * 64;
        ulonglong2 v_lo = *(const ulonglong2*)(vrow + lo_off);
        ulonglong2 v_hi = *(const ulonglong2*)(vrow + hi_off);
        float xr[2][4] = {{xA.x, xA.y, xA.z, xA.w}, {xB.x, xB.y, xB.z, xB.w}};
#pragma unroll
        for (int tk = 0; tk < 2; ++tk)
#pragma unroll
            for (int p = 0; p < 4; ++p) {
                float y = att[tk][p][0] * xr[tk][0] + att[tk][p][1] * xr[tk][1] +
                          att[tk][p][2] * xr[tk][2] + att[tk][p][3] * xr[tk][3];
                unsigned long long y2 = pack2(y, y);
                oa[tk][p][0] = fma2(y2, v_lo.x, oa[tk][p][0]);
                oa[tk][p][1] = fma2(y2, v_lo.y, oa[tk][p][1]);
                oa[tk][p][2] = fma2(y2, v_hi.x, oa[tk][p][2]);
                oa[tk][p][3] = fma2(y2, v_hi.y, oa[tk][p][3]);
            }
    }

    // x_s becomes o_s
    __syncthreads();
#pragma unroll
    for (int tk = 0; tk < 2; ++tk)
#pragma unroll
        for (int p = 0; p < 4; ++p)
#pragma unroll
            for (int i = 0; i < 4; ++i) {
                float lo, hi;
                unpack2(oa[tk][p][i], lo, hi);
                x_s[(h * 8 + 2 * i) * 256 + (t0 + tk) * 4 + p] = lo;
                x_s[(h * 8 + 2 * i + 1) * 256 + (t0 + tk) * 4 + p] = hi;
            }
    __syncthreads();

    // ===== phase 3: projection =====
    unsigned long long acc[2][4][4];
    {
        ulonglong2 b0 = *(const ulonglong2*)(sb + h * 8);
        ulonglong2 b1 = *(const ulonglong2*)(sb + h * 8 + 4);
#pragma unroll
        for (int tk = 0; tk < 2; ++tk)
#pragma unroll
            for (int p = 0; p < 4; ++p) {
                acc[tk][p][0] = b0.x; acc[tk][p][1] = b0.y;
                acc[tk][p][2] = b1.x; acc[tk][p][3] = b1.y;
            }
    }
#pragma unroll 1
    for (int c = 0; c < 64; ++c) {
        const float* orow = x_s + c * 256 + t0 * 4;
        float4 oA = *(const float4*)(orow);
        float4 oB = *(const float4*)(orow + 4);
        const float* prow = sW + 12288 + c * 64;
        ulonglong2 p_lo = *(const ulonglong2*)(prow + lo_off);
        ulonglong2 p_hi = *(const ulonglong2*)(prow + hi_off);
        float orr[2][4] = {{oA.x, oA.y, oA.z, oA.w}, {oB.x, oB.y, oB.z, oB.w}};
#pragma unroll
        for (int tk = 0; tk < 2; ++tk)
#pragma unroll
            for (int p = 0; p < 4; ++p) {
                unsigned long long o2 = pack2(orr[tk][p], orr[tk][p]);
                acc[tk][p][0] = fma2(o2, p_lo.x, acc[tk][p][0]);
                acc[tk][p][1] = fma2(o2, p_lo.y, acc[tk][p][1]);
                acc[tk][p][2] = fma2(o2, p_hi.x, acc[tk][p][2]);
                acc[tk][p][3] = fma2(o2, p_hi.y, acc[tk][p][3]);
            }
    }

    // stage to out_s[(p*64+c)][t]
    __syncthreads();
#pragma unroll
    for (int tk = 0; tk < 2; ++tk)
#pragma unroll
        for (int p = 0; p < 4; ++p)
#pragma unroll
            for (int i = 0; i < 4; ++i) {
                float lo, hi;
                unpack2(acc[tk][p][i], lo, hi);
                x_s[(p * 64 + h * 8 + 2 * i) * 64 + t0 + tk] = lo;
                x_s[(p * 64 + h * 8 + 2 * i + 1) * 64 + t0 + tk] = hi;
            }
    __syncthreads();

    // coalesced float4 writeback
    for (int i4 = tid; i4 < 4096; i4 += 256) {
        int pc = i4 >> 4;
        int t4 = (i4 & 15) * 4;
        int p = pc >> 6, c = pc & 63;
        float4 v = *(const float4*)(x_s + pc * 64 + t4);
        *(float4*)(out + (size_t)((b * 4 + p) * 64 + c) * HW + pos0 + t4) = v;
    }
}

// ---------------------------------------------------------------------------
extern "C" void kernel_launch(void* const* d_in, const int* in_sizes, int n_in,
                              void* d_out, int out_size) {
    (void)in_sizes; (void)n_in; (void)out_size;
    const float* x_in   = (const float*)d_in[0];
    const float* mask   = (const float*)d_in[1];
    const float* wq     = (const float*)d_in[2];
    const float* wk     = (const float*)d_in[3];
    const float* wv     = (const float*)d_in[4];
    const float* w_proj = (const float*)d_in[5];
    const float* b_proj = (const float*)d_in[6];
    const float* rescale= (const float*)d_in[7];
    const float* dw_w   = (const float*)d_in[8];
    const float* dw_b   = (const float*)d_in[9];
    const float* pw_w   = (const float*)d_in[10];
    const float* pw_b   = (const float*)d_in[11];
    float* out = (float*)d_out;

    cudaFuncSetAttribute(attn_kernel,
                         cudaFuncAttributeMaxDynamicSharedMemorySize,
                         SMEM_FLOATS * sizeof(float));

    mask_kernel2<<<dim3(8, 8, 16), dim3(16, 16)>>>(mask, dw_w, dw_b, pw_w, pw_b);
    attn_kernel<<<dim3(HW / TOK, Bn), 256, SMEM_FLOATS * sizeof(float)>>>(
        x_in, wq, wk, wv, w_proj, b_proj, rescale, out);
}

// round 5
// speedup vs baseline: 1.9102x; 1.0159x over previous
#include <cuda_runtime.h>
#include <math.h>

#define Bn 4
#define Pp 4
#define Cc 64
#define NH 8
#define DH 8
#define Hh 128
#define Wd 128
#define HW 16384
#define TOK 64

// scratch (no cudaMalloc allowed)
__device__ float g_mb[16 * HW];     // [(b*4+p)][pos] mask-bias

// ---------------------------------------------------------------------------
// packed f32x2 helpers
// ---------------------------------------------------------------------------
__device__ __forceinline__ unsigned long long fma2(unsigned long long a,
                                                   unsigned long long b,
                                                   unsigned long long c) {
    unsigned long long d;
    asm("fma.rn.f32x2 %0, %1, %2, %3;" : "=l"(d) : "l"(a), "l"(b), "l"(c));
    return d;
}
__device__ __forceinline__ unsigned long long mul2(unsigned long long a,
                                                   unsigned long long b) {
    unsigned long long d;
    asm("mul.rn.f32x2 %0, %1, %2;" : "=l"(d) : "l"(a), "l"(b));
    return d;
}
__device__ __forceinline__ unsigned long long pack2(float lo, float hi) {
    unsigned long long d;
    asm("mov.b64 %0, {%1, %2};" : "=l"(d) : "f"(lo), "f"(hi));
    return d;
}
__device__ __forceinline__ void unpack2(unsigned long long v, float& lo, float& hi) {
    asm("mov.b64 {%0, %1}, %2;" : "=f"(lo), "=f"(hi) : "l"(v));
}

// ---------------------------------------------------------------------------
// Kernel 1: mask branch, 4 channels per barrier round (latency batching).
// ---------------------------------------------------------------------------
__global__ void mask_kernel2(const float* __restrict__ mask,
                             const float* __restrict__ dw_w,
                             const float* __restrict__ dw_b,
                             const float* __restrict__ pw_w,
                             const float* __restrict__ pw_b) {
    __shared__ float tile[4][18][20];
    __shared__ float sdw[Cc][9];
    __shared__ float sdb[Cc];
    __shared__ float swbar[Cc + 1];
    __shared__ float wpart[4][Cc];

    int bp = blockIdx.z;
    int h0 = blockIdx.y * 16, w0 = blockIdx.x * 16;
    int tx = threadIdx.x, ty = threadIdx.y;
    int tid = ty * 16 + tx;

    for (int i = tid; i < Cc * 9; i += 256) sdw[i / 9][i % 9] = dw_w[i];
    for (int i = tid; i < Cc; i += 256) sdb[i] = dw_b[i];
    {
        int c = tid & 63, dg = tid >> 6;
        float s = 0.f;
        for (int d = dg * 16; d < dg * 16 + 16; ++d) s += pw_w[d * Cc + c];
        wpart[dg][c] = s;
    }
    if (tid >= 192) {
        float s = pw_b[tid - 192];
#pragma unroll
        for (int o = 16; o > 0; o >>= 1)
            s += __shfl_down_sync(0xFFFFFFFFu, s, o);
        if (tid == 192) swbar[Cc] = s * (1.0f / Cc);
    }
    __syncthreads();
    if (tid < Cc)
        swbar[tid] = (wpart[0][tid] + wpart[1][tid] + wpart[2][tid] + wpart[3][tid]) * (1.0f / Cc);

    float acc = 0.f;
    const float* base = mask + (size_t)bp * Cc * HW;

    for (int cb = 0; cb < Cc; cb += 4) {
        __syncthreads();
        for (int i = tid; i < 4 * 324; i += 256) {
            int cc = i / 324, r = i % 324;
            int hy = r / 18, wx = r % 18;
            int gh = h0 + hy - 1, gw = w0 + wx - 1;
            float v = 0.f;
            if (gh >= 0 && gh < Hh && gw >= 0 && gw < Wd)
                v = base[(size_t)(cb + cc) * HW + gh * Wd + gw];
            tile[cc][hy][wx] = v;
        }
        __syncthreads();
#pragma unroll
        for (int cc = 0; cc < 4; ++cc) {
            int c = cb + cc;
            float y = sdb[c];
#pragma unroll
            for (int dy = 0; dy < 3; ++dy)
#pragma unroll
                for (int dx = 0; dx < 3; ++dx)
                    y += tile[cc][ty + dy][tx + dx] * sdw[c][dy * 3 + dx];
            float g = 0.5f * y * (1.0f + erff(y * 0.70710678118654752f));
            acc += swbar[c] * g;
        }
    }
    acc += swbar[Cc];
    g_mb[(size_t)bp * HW + (h0 + ty) * Wd + (w0 + tx)] = acc;
}

// ---------------------------------------------------------------------------
// Kernel 2: 64 tokens/block, 2 tokens/thread, swizzled weights,
// software-pipelined smem loads (prefetch c+1 while computing c).
// smem layout identical to R4: 33096 floats.
// ---------------------------------------------------------------------------
#define SMEM_FLOATS 33096

__global__ void __launch_bounds__(256, 1)
attn_kernel(const float* __restrict__ x_in,
            const float* __restrict__ wq,
            const float* __restrict__ wk,
            const float* __restrict__ wv,
            const float* __restrict__ wp,
            const float* __restrict__ b_proj,
            const float* __restrict__ rescale,
            float* __restrict__ out) {
    extern __shared__ float sm[];
    float* sW   = sm;
    float* x_s  = sm + 16384;   // aliased o_s / out_s
    float* mb_s = sm + 32768;
    float* sb   = sm + 33024;
    float* sr   = sm + 33088;

    int tid = threadIdx.x;
    int b = blockIdx.y;
    int pos0 = blockIdx.x * TOK;

    // --- stage weights swizzled ---
    const float* Ws[4] = {wq, wk, wv, wp};
#pragma unroll
    for (int m = 0; m < 4; ++m) {
        for (int i4 = tid; i4 < 1024; i4 += 256) {
            int d = i4 >> 4, c4 = (i4 & 15) * 4;
            float4 w4 = *(const float4*)(Ws[m] + d * 64 + c4);
            int hq = d >> 3;
            int grp = (d >> 2) & 1;
            int gsw = (hq >= 4) ? (1 - grp) : grp;
            int pos = hq * 8 + gsw * 4 + (d & 3);
            float* dst = sW + m * 4096 + c4 * 64 + pos;
            dst[0] = w4.x; dst[64] = w4.y; dst[128] = w4.z; dst[192] = w4.w;
        }
    }
    // --- stage x as x_s[c][t][p] ---
    for (int i4 = tid; i4 < 4096; i4 += 256) {
        int pc = i4 >> 4;
        int t4 = (i4 & 15) * 4;
        int p = pc >> 6, c = pc & 63;
        float4 xv = *(const float4*)(x_in + (size_t)((b * 4 + p) * 64 + c) * HW + pos0 + t4);
        float* dst = x_s + c * 256 + t4 * 4 + p;
        dst[0] = xv.x; dst[4] = xv.y; dst[8] = xv.z; dst[12] = xv.w;
    }
    {
        int p = tid >> 6, t = tid & 63;
        mb_s[t * 4 + p] = g_mb[(size_t)(b * 4 + p) * HW + pos0 + t];
    }
    if (tid < 64) sb[tid] = b_proj[tid];
    if (tid < 8) sr[tid] = rescale[tid];
    __syncthreads();

    const int h = tid & 7;
    const int tp = tid >> 3;
    const int t0 = tp * 2;
    const int lo_off = h * 8 + ((h & 4) ? 4 : 0);
    const int hi_off = h * 8 + ((h & 4) ? 0 : 4);

    const float* xb = x_s + t0 * 4;
    const float* qb = sW;
    const float* kb = sW + 4096;
    const float* vb = sW + 8192;
    const float* pb = sW + 12288;

    // ===== phase 1: Q,K (pipelined) =====
    unsigned long long qa[2][4][4], ka[2][4][4];
#pragma unroll
    for (int tk = 0; tk < 2; ++tk)
#pragma unroll
        for (int p = 0; p < 4; ++p)
#pragma unroll
            for (int i = 0; i < 4; ++i) { qa[tk][p][i] = 0ULL; ka[tk][p][i] = 0ULL; }

    {
        float4 xA = *(const float4*)(xb);
        float4 xB = *(const float4*)(xb + 4);
        ulonglong2 q_lo = *(const ulonglong2*)(qb + lo_off);
        ulonglong2 q_hi = *(const ulonglong2*)(qb + hi_off);
        ulonglong2 k_lo = *(const ulonglong2*)(kb + lo_off);
        ulonglong2 k_hi = *(const ulonglong2*)(kb + hi_off);
#pragma unroll 2
        for (int c = 0; c < 64; ++c) {
            float4 nxA, nxB;
            ulonglong2 nq_lo, nq_hi, nk_lo, nk_hi;
            if (c < 63) {
                const float* xr_ = xb + (c + 1) * 256;
                nxA = *(const float4*)(xr_);
                nxB = *(const float4*)(xr_ + 4);
                const float* qr_ = qb + (c + 1) * 64;
                const float* kr_ = kb + (c + 1) * 64;
                nq_lo = *(const ulonglong2*)(qr_ + lo_off);
                nq_hi = *(const ulonglong2*)(qr_ + hi_off);
                nk_lo = *(const ulonglong2*)(kr_ + lo_off);
                nk_hi = *(const ulonglong2*)(kr_ + hi_off);
            }
            float xr[2][4] = {{xA.x, xA.y, xA.z, xA.w}, {xB.x, xB.y, xB.z, xB.w}};
#pragma unroll
            for (int tk = 0; tk < 2; ++tk)
#pragma unroll
                for (int p = 0; p < 4; ++p) {
                    unsigned long long xp2 = pack2(xr[tk][p], xr[tk][p]);
                    qa[tk][p][0] = fma2(xp2, q_lo.x, qa[tk][p][0]);
                    qa[tk][p][1] = fma2(xp2, q_lo.y, qa[tk][p][1]);
                    qa[tk][p][2] = fma2(xp2, q_hi.x, qa[tk][p][2]);
                    qa[tk][p][3] = fma2(xp2, q_hi.y, qa[tk][p][3]);
                    ka[tk][p][0] = fma2(xp2, k_lo.x, ka[tk][p][0]);
                    ka[tk][p][1] = fma2(xp2, k_lo.y, ka[tk][p][1]);
                    ka[tk][p][2] = fma2(xp2, k_hi.x, ka[tk][p][2]);
                    ka[tk][p][3] = fma2(xp2, k_hi.y, ka[tk][p][3]);
                }
            xA = nxA; xB = nxB;
            q_lo = nq_lo; q_hi = nq_hi; k_lo = nk_lo; k_hi = nk_hi;
        }
    }

    // ===== normalize + scores + softmax =====
    float att[2][4][4];
    float rh = sr[h];
#pragma unroll
    for (int tk = 0; tk < 2; ++tk) {
#pragma unroll
        for (int p = 0; p < 4; ++p) {
            unsigned long long s2q = 0ULL, s2k = 0ULL;
#pragma unroll
            for (int i = 0; i < 4; ++i) {
                s2q = fma2(qa[tk][p][i], qa[tk][p][i], s2q);
                s2k = fma2(ka[tk][p][i], ka[tk][p][i], s2k);
            }
            float qlo, qhi, klo, khi;
            unpack2(s2q, qlo, qhi);
            unpack2(s2k, klo, khi);
            float iq = 1.0f / fmaxf(sqrtf(qlo + qhi), 1e-12f);
            float ik = 1.0f / fmaxf(sqrtf(klo + khi), 1e-12f);
            unsigned long long iq2 = pack2(iq, iq);
            unsigned long long ik2 = pack2(ik, ik);
#pragma unroll
            for (int i = 0; i < 4; ++i) {
                qa[tk][p][i] = mul2(qa[tk][p][i], iq2);
                ka[tk][p][i] = mul2(ka[tk][p][i], ik2);
            }
        }
        float mbl[4];
#pragma unroll
        for (int p = 0; p < 4; ++p) mbl[p] = mb_s[(t0 + tk) * 4 + p];
#pragma unroll
        for (int p = 0; p < 4; ++p) {
#pragma unroll
            for (int pq = 0; pq < 4; ++pq) {
                unsigned long long d2 = 0ULL;
#pragma unroll
                for (int i = 0; i < 4; ++i) d2 = fma2(qa[tk][p][i], ka[tk][pq][i], d2);
                float lo, hi;
                unpack2(d2, lo, hi);
                att[tk][p][pq] = (lo + hi) * rh + (mbl[pq] - mbl[p]);
            }
            float mx = fmaxf(fmaxf(att[tk][p][0], att[tk][p][1]),
                             fmaxf(att[tk][p][2], att[tk][p][3]));
            float s = 0.f;
#pragma unroll
            for (int pq = 0; pq < 4; ++pq) {
                att[tk][p][pq] = __expf(att[tk][p][pq] - mx);
                s += att[tk][p][pq];
            }
            float inv = 1.0f / s;
#pragma unroll
            for (int pq = 0; pq < 4; ++pq) att[tk][p][pq] *= inv;
        }
    }

    // packed att pairs: attp[tk][g][pq] = pack2(att[2g], att[2g+1])
    unsigned long long attp[2][2][4];
#pragma unroll
    for (int tk = 0; tk < 2; ++tk)
#pragma unroll
        for (int g = 0; g < 2; ++g)
#pragma unroll
            for (int pq = 0; pq < 4; ++pq)
                attp[tk][g][pq] = pack2(att[tk][2 * g][pq], att[tk][2 * g + 1][pq]);

    // ===== phase 2: fused AV (pipelined, packed y) =====
    unsigned long long oa[2][4][4];
#pragma unroll
    for (int tk = 0; tk < 2; ++tk)
#pragma unroll
        for (int p = 0; p < 4; ++p)
#pragma unroll
            for (int i = 0; i < 4; ++i) oa[tk][p][i] = 0ULL;

    {
        float4 xA = *(const float4*)(xb);
        float4 xB = *(const float4*)(xb + 4);
        ulonglong2 v_lo = *(const ulonglong2*)(vb + lo_off);
        ulonglong2 v_hi = *(const ulonglong2*)(vb + hi_off);
#pragma unroll 2
        for (int c = 0; c < 64; ++c) {
            float4 nxA, nxB;
            ulonglong2 nv_lo, nv_hi;
            if (c < 63) {
                const float* xr_ = xb + (c + 1) * 256;
                nxA = *(const float4*)(xr_);
                nxB = *(const float4*)(xr_ + 4);
                const float* vr_ = vb + (c + 1) * 64;
                nv_lo = *(const ulonglong2*)(vr_ + lo_off);
                nv_hi = *(const ulonglong2*)(vr_ + hi_off);
            }
            float xr[2][4] = {{xA.x, xA.y, xA.z, xA.w}, {xB.x, xB.y, xB.z, xB.w}};
#pragma unroll
            for (int tk = 0; tk < 2; ++tk) {
                unsigned long long x2[4];
#pragma unroll
                for (int pq = 0; pq < 4; ++pq) x2[pq] = pack2(xr[tk][pq], xr[tk][pq]);
                unsigned long long y01 = 0ULL, y23 = 0ULL;
#pragma unroll
                for (int pq = 0; pq < 4; ++pq) {
                    y01 = fma2(attp[tk][0][pq], x2[pq], y01);
                    y23 = fma2(attp[tk][1][pq], x2[pq], y23);
                }
                float y0, y1, y2, y3;
                unpack2(y01, y0, y1);
                unpack2(y23, y2, y3);
                float yv[4] = {y0, y1, y2, y3};
#pragma unroll
                for (int p = 0; p < 4; ++p) {
                    unsigned long long y2b = pack2(yv[p], yv[p]);
                    oa[tk][p][0] = fma2(y2b, v_lo.x, oa[tk][p][0]);
                    oa[tk][p][1] = fma2(y2b, v_lo.y, oa[tk][p][1]);
                    oa[tk][p][2] = fma2(y2b, v_hi.x, oa[tk][p][2]);
                    oa[tk][p][3] = fma2(y2b, v_hi.y, oa[tk][p][3]);
                }
            }
            xA = nxA; xB = nxB; v_lo = nv_lo; v_hi = nv_hi;
        }
    }

    // x_s becomes o_s
    __syncthreads();
#pragma unroll
    for (int tk = 0; tk < 2; ++tk)
#pragma unroll
        for (int p = 0; p < 4; ++p)
#pragma unroll
            for (int i = 0; i < 4; ++i) {
                float lo, hi;
                unpack2(oa[tk][p][i], lo, hi);
                x_s[(h * 8 + 2 * i) * 256 + (t0 + tk) * 4 + p] = lo;
                x_s[(h * 8 + 2 * i + 1) * 256 + (t0 + tk) * 4 + p] = hi;
            }
    __syncthreads();

    // ===== phase 3: projection (pipelined) =====
    unsigned long long acc[2][4][4];
    {
        ulonglong2 b0 = *(const ulonglong2*)(sb + h * 8);
        ulonglong2 b1 = *(const ulonglong2*)(sb + h * 8 + 4);
#pragma unroll
        for (int tk = 0; tk < 2; ++tk)
#pragma unroll
            for (int p = 0; p < 4; ++p) {
                acc[tk][p][0] = b0.x; acc[tk][p][1] = b0.y;
                acc[tk][p][2] = b1.x; acc[tk][p][3] = b1.y;
            }
    }
    {
        float4 oA = *(const float4*)(xb);
        float4 oB = *(const float4*)(xb + 4);
        ulonglong2 p_lo = *(const ulonglong2*)(pb + lo_off);
        ulonglong2 p_hi = *(const ulonglong2*)(pb + hi_off);
#pragma unroll 2
        for (int c = 0; c < 64; ++c) {
            float4 noA, noB;
            ulonglong2 np_lo, np_hi;
            if (c < 63) {
                const float* or_ = xb + (c + 1) * 256;
                noA = *(const float4*)(or_);
                noB = *(const float4*)(or_ + 4);
                const float* pr_ = pb + (c + 1) * 64;
                np_lo = *(const ulonglong2*)(pr_ + lo_off);
                np_hi = *(const ulonglong2*)(pr_ + hi_off);
            }
            float orr[2][4] = {{oA.x, oA.y, oA.z, oA.w}, {oB.x, oB.y, oB.z, oB.w}};
#pragma unroll
            for (int tk = 0; tk < 2; ++tk)
#pragma unroll
                for (int p = 0; p < 4; ++p) {
                    unsigned long long o2 = pack2(orr[tk][p], orr[tk][p]);
                    acc[tk][p][0] = fma2(o2, p_lo.x, acc[tk][p][0]);
                    acc[tk][p][1] = fma2(o2, p_lo.y, acc[tk][p][1]);
                    acc[tk][p][2] = fma2(o2, p_hi.x, acc[tk][p][2]);
                    acc[tk][p][3] = fma2(o2, p_hi.y, acc[tk][p][3]);
                }
            oA = noA; oB = noB; p_lo = np_lo; p_hi = np_hi;
        }
    }

    // stage to out_s[(p*64+c)][t]
    __syncthreads();
#pragma unroll
    for (int tk = 0; tk < 2; ++tk)
#pragma unroll
        for (int p = 0; p < 4; ++p)
#pragma unroll
            for (int i = 0; i < 4; ++i) {
                float lo, hi;
                unpack2(acc[tk][p][i], lo, hi);
                x_s[(p * 64 + h * 8 + 2 * i) * 64 + t0 + tk] = lo;
                x_s[(p * 64 + h * 8 + 2 * i + 1) * 64 + t0 + tk] = hi;
            }
    __syncthreads();

    // coalesced float4 writeback
    for (int i4 = tid; i4 < 4096; i4 += 256) {
        int pc = i4 >> 4;
        int t4 = (i4 & 15) * 4;
        int p = pc >> 6, c = pc & 63;
        float4 v = *(const float4*)(x_s + pc * 64 + t4);
        *(float4*)(out + (size_t)((b * 4 + p) * 64 + c) * HW + pos0 + t4) = v;
    }
}

// ---------------------------------------------------------------------------
extern "C" void kernel_launch(void* const* d_in, const int* in_sizes, int n_in,
                              void* d_out, int out_size) {
    (void)in_sizes; (void)n_in; (void)out_size;
    const float* x_in   = (const float*)d_in[0];
    const float* mask   = (const float*)d_in[1];
    const float* wq     = (const float*)d_in[2];
    const float* wk     = (const float*)d_in[3];
    const float* wv     = (const float*)d_in[4];
    const float* w_proj = (const float*)d_in[5];
    const float* b_proj = (const float*)d_in[6];
    const float* rescale= (const float*)d_in[7];
    const float* dw_w   = (const float*)d_in[8];
    const float* dw_b   = (const float*)d_in[9];
    const float* pw_w   = (const float*)d_in[10];
    const float* pw_b   = (const float*)d_in[11];
    float* out = (float*)d_out;

    cudaFuncSetAttribute(attn_kernel,
                         cudaFuncAttributeMaxDynamicSharedMemorySize,
                         SMEM_FLOATS * sizeof(float));

    mask_kernel2<<<dim3(8, 8, 16), dim3(16, 16)>>>(mask, dw_w, dw_b, pw_w, pw_b);
    attn_kernel<<<dim3(HW / TOK, Bn), 256, SMEM_FLOATS * sizeof(float)>>>(
        x_in, wq, wk, wv, w_proj, b_proj, rescale, out);
}

// round 6
// speedup vs baseline: 2.0447x; 1.0704x over previous
#include <cuda_runtime.h>
#include <math.h>

#define Bn 4
#define Pp 4
#define Cc 64
#define NH 8
#define DH 8
#define Hh 128
#define Wd 128
#define HW 16384
#define TOK 32

// scratch (no cudaMalloc allowed)
__device__ float g_mb[16 * HW];     // [(b*4+p)][pos] mask-bias

// ---------------------------------------------------------------------------
// packed f32x2 helpers
// ---------------------------------------------------------------------------
__device__ __forceinline__ unsigned long long fma2(unsigned long long a,
                                                   unsigned long long b,
                                                   unsigned long long c) {
    unsigned long long d;
    asm("fma.rn.f32x2 %0, %1, %2, %3;" : "=l"(d) : "l"(a), "l"(b), "l"(c));
    return d;
}
__device__ __forceinline__ unsigned long long mul2(unsigned long long a,
                                                   unsigned long long b) {
    unsigned long long d;
    asm("mul.rn.f32x2 %0, %1, %2;" : "=l"(d) : "l"(a), "l"(b));
    return d;
}
__device__ __forceinline__ unsigned long long pack2(float lo, float hi) {
    unsigned long long d;
    asm("mov.b64 %0, {%1, %2};" : "=l"(d) : "f"(lo), "f"(hi));
    return d;
}
__device__ __forceinline__ void unpack2(unsigned long long v, float& lo, float& hi) {
    asm("mov.b64 {%0, %1}, %2;" : "=f"(lo), "=f"(hi) : "l"(v));
}

// ---------------------------------------------------------------------------
// Kernel 1: mask branch, 8 channels per barrier round.
// ---------------------------------------------------------------------------
__global__ void mask_kernel2(const float* __restrict__ mask,
                             const float* __restrict__ dw_w,
                             const float* __restrict__ dw_b,
                             const float* __restrict__ pw_w,
                             const float* __restrict__ pw_b) {
    __shared__ float tile[8][18][20];
    __shared__ float sdw[Cc][9];
    __shared__ float sdb[Cc];
    __shared__ float swbar[Cc + 1];
    __shared__ float wpart[4][Cc];

    int bp = blockIdx.z;
    int h0 = blockIdx.y * 16, w0 = blockIdx.x * 16;
    int tx = threadIdx.x, ty = threadIdx.y;
    int tid = ty * 16 + tx;

    for (int i = tid; i < Cc * 9; i += 256) sdw[i / 9][i % 9] = dw_w[i];
    for (int i = tid; i < Cc; i += 256) sdb[i] = dw_b[i];
    {
        int c = tid & 63, dg = tid >> 6;
        float s = 0.f;
        for (int d = dg * 16; d < dg * 16 + 16; ++d) s += pw_w[d * Cc + c];
        wpart[dg][c] = s;
    }
    if (tid >= 192) {
        float s = pw_b[tid - 192];
#pragma unroll
        for (int o = 16; o > 0; o >>= 1)
            s += __shfl_down_sync(0xFFFFFFFFu, s, o);
        if (tid == 192) swbar[Cc] = s * (1.0f / Cc);
    }
    __syncthreads();
    if (tid < Cc)
        swbar[tid] = (wpart[0][tid] + wpart[1][tid] + wpart[2][tid] + wpart[3][tid]) * (1.0f / Cc);

    float acc = 0.f;
    const float* base = mask + (size_t)bp * Cc * HW;

    for (int cb = 0; cb < Cc; cb += 8) {
        __syncthreads();
        for (int i = tid; i < 8 * 324; i += 256) {
            int cc = i / 324, r = i % 324;
            int hy = r / 18, wx = r % 18;
            int gh = h0 + hy - 1, gw = w0 + wx - 1;
            float v = 0.f;
            if (gh >= 0 && gh < Hh && gw >= 0 && gw < Wd)
                v = base[(size_t)(cb + cc) * HW + gh * Wd + gw];
            tile[cc][hy][wx] = v;
        }
        __syncthreads();
#pragma unroll
        for (int cc = 0; cc < 8; ++cc) {
            int c = cb + cc;
            float y = sdb[c];
#pragma unroll
            for (int dy = 0; dy < 3; ++dy)
#pragma unroll
                for (int dx = 0; dx < 3; ++dx)
                    y += tile[cc][ty + dy][tx + dx] * sdw[c][dy * 3 + dx];
            float g = 0.5f * y * (1.0f + erff(y * 0.70710678118654752f));
            acc += swbar[c] * g;
        }
    }
    acc += swbar[Cc];
    g_mb[(size_t)bp * HW + (h0 + ty) * Wd + (w0 + tx)] = acc;
}

// ---------------------------------------------------------------------------
// Kernel 2: 32 tokens/block, 1 token/thread, swizzled weights,
// PER-PHASE weight staging -> 65 KB smem -> 2 CTAs/SM (4 warps/SMSP).
// smem (floats):
//   sWA [64][64]   0      wq -> wv
//   sWB [64][64]   4096   wk -> wp
//   x_s [64][32][4] 8192  (aliased o_s, out staging [256][32])
//   mb_s[32][4]    16384
//   sb  [64]       16512
//   sr  [8]        16576
// total = 16584 floats = 66336 B
// ---------------------------------------------------------------------------
#define SMEM_FLOATS 16584

__device__ __forceinline__ void stage_w(float* dst, const float* __restrict__ src,
                                        int tid) {
    for (int i4 = tid; i4 < 1024; i4 += 256) {
        int d = i4 >> 4, c4 = (i4 & 15) * 4;
        float4 w4 = *(const float4*)(src + d * 64 + c4);
        int hq = d >> 3;
        int grp = (d >> 2) & 1;
        int gsw = (hq >= 4) ? (1 - grp) : grp;
        int pos = hq * 8 + gsw * 4 + (d & 3);
        float* p = dst + c4 * 64 + pos;
        p[0] = w4.x; p[64] = w4.y; p[128] = w4.z; p[192] = w4.w;
    }
}

__global__ void __launch_bounds__(256, 2)
attn_kernel(const float* __restrict__ x_in,
            const float* __restrict__ wq,
            const float* __restrict__ wk,
            const float* __restrict__ wv,
            const float* __restrict__ wp,
            const float* __restrict__ b_proj,
            const float* __restrict__ rescale,
            float* __restrict__ out) {
    extern __shared__ float sm[];
    float* sWA  = sm;
    float* sWB  = sm + 4096;
    float* x_s  = sm + 8192;
    float* mb_s = sm + 16384;
    float* sb   = sm + 16512;
    float* sr   = sm + 16576;

    int tid = threadIdx.x;
    int b = blockIdx.y;
    int pos0 = blockIdx.x * TOK;

    stage_w(sWA, wq, tid);
    stage_w(sWB, wk, tid);
    // stage x as x_s[c][t][p]
    for (int i4 = tid; i4 < 2048; i4 += 256) {
        int pc = i4 >> 3;              // p*64+c
        int t4 = (i4 & 7) * 4;
        int p = pc >> 6, c = pc & 63;
        float4 xv = *(const float4*)(x_in + (size_t)((b * 4 + p) * 64 + c) * HW + pos0 + t4);
        float* dst = x_s + c * 128 + t4 * 4 + p;
        dst[0] = xv.x; dst[4] = xv.y; dst[8] = xv.z; dst[12] = xv.w;
    }
    if (tid < 128) {
        int p = tid >> 5, t = tid & 31;
        mb_s[t * 4 + p] = g_mb[(size_t)(b * 4 + p) * HW + pos0 + t];
    }
    if (tid < 64) sb[tid] = b_proj[tid];
    if (tid < 8) sr[tid] = rescale[tid];
    __syncthreads();

    const int h = tid & 7;
    const int t = tid >> 3;
    const int lo_off = h * 8 + ((h & 4) ? 4 : 0);
    const int hi_off = h * 8 + ((h & 4) ? 0 : 4);
    const float* xb = x_s + t * 4;

    // ===== phase 1: Q,K =====
    unsigned long long qa[4][4], ka[4][4];
#pragma unroll
    for (int p = 0; p < 4; ++p)
#pragma unroll
        for (int i = 0; i < 4; ++i) { qa[p][i] = 0ULL; ka[p][i] = 0ULL; }

#pragma unroll 2
    for (int c = 0; c < 64; ++c) {
        float4 xv = *(const float4*)(xb + c * 128);
        const float* qrow = sWA + c * 64;
        const float* krow = sWB + c * 64;
        ulonglong2 q_lo = *(const ulonglong2*)(qrow + lo_off);
        ulonglong2 q_hi = *(const ulonglong2*)(qrow + hi_off);
        ulonglong2 k_lo = *(const ulonglong2*)(krow + lo_off);
        ulonglong2 k_hi = *(const ulonglong2*)(krow + hi_off);
        float xr[4] = {xv.x, xv.y, xv.z, xv.w};
#pragma unroll
        for (int p = 0; p < 4; ++p) {
            unsigned long long xp2 = pack2(xr[p], xr[p]);
            qa[p][0] = fma2(xp2, q_lo.x, qa[p][0]);
            qa[p][1] = fma2(xp2, q_lo.y, qa[p][1]);
            qa[p][2] = fma2(xp2, q_hi.x, qa[p][2]);
            qa[p][3] = fma2(xp2, q_hi.y, qa[p][3]);
            ka[p][0] = fma2(xp2, k_lo.x, ka[p][0]);
            ka[p][1] = fma2(xp2, k_lo.y, ka[p][1]);
            ka[p][2] = fma2(xp2, k_hi.x, ka[p][2]);
            ka[p][3] = fma2(xp2, k_hi.y, ka[p][3]);
        }
    }

    // ===== normalize + scores + softmax =====
    float att[4][4];
    float rh = sr[h];
#pragma unroll
    for (int p = 0; p < 4; ++p) {
        unsigned long long s2q = 0ULL, s2k = 0ULL;
#pragma unroll
        for (int i = 0; i < 4; ++i) {
            s2q = fma2(qa[p][i], qa[p][i], s2q);
            s2k = fma2(ka[p][i], ka[p][i], s2k);
        }
        float qlo, qhi, klo, khi;
        unpack2(s2q, qlo, qhi);
        unpack2(s2k, klo, khi);
        float iq = 1.0f / fmaxf(sqrtf(qlo + qhi), 1e-12f);
        float ik = 1.0f / fmaxf(sqrtf(klo + khi), 1e-12f);
        unsigned long long iq2 = pack2(iq, iq);
        unsigned long long ik2 = pack2(ik, ik);
#pragma unroll
        for (int i = 0; i < 4; ++i) {
            qa[p][i] = mul2(qa[p][i], iq2);
            ka[p][i] = mul2(ka[p][i], ik2);
        }
    }
    {
        float mbl[4];
#pragma unroll
        for (int p = 0; p < 4; ++p) mbl[p] = mb_s[t * 4 + p];
#pragma unroll
        for (int p = 0; p < 4; ++p) {
#pragma unroll
            for (int pq = 0; pq < 4; ++pq) {
                unsigned long long d2 = 0ULL;
#pragma unroll
                for (int i = 0; i < 4; ++i) d2 = fma2(qa[p][i], ka[pq][i], d2);
                float lo, hi;
                unpack2(d2, lo, hi);
                att[p][pq] = (lo + hi) * rh + (mbl[pq] - mbl[p]);
            }
            float mx = fmaxf(fmaxf(att[p][0], att[p][1]),
                             fmaxf(att[p][2], att[p][3]));
            float s = 0.f;
#pragma unroll
            for (int pq = 0; pq < 4; ++pq) {
                att[p][pq] = __expf(att[p][pq] - mx);
                s += att[p][pq];
            }
            float inv = 1.0f / s;
#pragma unroll
            for (int pq = 0; pq < 4; ++pq) att[p][pq] *= inv;
        }
    }

    // packed att pairs for y computation
    unsigned long long attp[2][4];
#pragma unroll
    for (int g = 0; g < 2; ++g)
#pragma unroll
        for (int pq = 0; pq < 4; ++pq)
            attp[g][pq] = pack2(att[2 * g][pq], att[2 * g + 1][pq]);

    // ===== restage wv into sWA =====
    __syncthreads();
    stage_w(sWA, wv, tid);
    __syncthreads();

    // ===== phase 2: fused AV =====
    unsigned long long oa[4][4];
#pragma unroll
    for (int p = 0; p < 4; ++p)
#pragma unroll
        for (int i = 0; i < 4; ++i) oa[p][i] = 0ULL;

#pragma unroll 2
    for (int c = 0; c < 64; ++c) {
        float4 xv = *(const float4*)(xb + c * 128);
        const float* vrow = sWA + c * 64;
        ulonglong2 v_lo = *(const ulonglong2*)(vrow + lo_off);
        ulonglong2 v_hi = *(const ulonglong2*)(vrow + hi_off);
        unsigned long long x2[4];
        x2[0] = pack2(xv.x, xv.x); x2[1] = pack2(xv.y, xv.y);
        x2[2] = pack2(xv.z, xv.z); x2[3] = pack2(xv.w, xv.w);
        unsigned long long y01 = 0ULL, y23 = 0ULL;
#pragma unroll
        for (int pq = 0; pq < 4; ++pq) {
            y01 = fma2(attp[0][pq], x2[pq], y01);
            y23 = fma2(attp[1][pq], x2[pq], y23);
        }
        float y0, y1, y2, y3;
        unpack2(y01, y0, y1);
        unpack2(y23, y2, y3);
        float yv[4] = {y0, y1, y2, y3};
#pragma unroll
        for (int p = 0; p < 4; ++p) {
            unsigned long long y2b = pack2(yv[p], yv[p]);
            oa[p][0] = fma2(y2b, v_lo.x, oa[p][0]);
            oa[p][1] = fma2(y2b, v_lo.y, oa[p][1]);
            oa[p][2] = fma2(y2b, v_hi.x, oa[p][2]);
            oa[p][3] = fma2(y2b, v_hi.y, oa[p][3]);
        }
    }

    // x_s becomes o_s; restage wp into sWB
    __syncthreads();
#pragma unroll
    for (int p = 0; p < 4; ++p)
#pragma unroll
        for (int i = 0; i < 4; ++i) {
            float lo, hi;
            unpack2(oa[p][i], lo, hi);
            x_s[(h * 8 + 2 * i) * 128 + t * 4 + p] = lo;
            x_s[(h * 8 + 2 * i + 1) * 128 + t * 4 + p] = hi;
        }
    stage_w(sWB, wp, tid);
    __syncthreads();

    // ===== phase 3: projection =====
    unsigned long long acc[4][4];
    {
        ulonglong2 b0 = *(const ulonglong2*)(sb + h * 8);
        ulonglong2 b1 = *(const ulonglong2*)(sb + h * 8 + 4);
#pragma unroll
        for (int p = 0; p < 4; ++p) {
            acc[p][0] = b0.x; acc[p][1] = b0.y;
            acc[p][2] = b1.x; acc[p][3] = b1.y;
        }
    }
#pragma unroll 2
    for (int c = 0; c < 64; ++c) {
        float4 ov = *(const float4*)(xb + c * 128);
        const float* prow = sWB + c * 64;
        ulonglong2 p_lo = *(const ulonglong2*)(prow + lo_off);
        ulonglong2 p_hi = *(const ulonglong2*)(prow + hi_off);
        float orr[4] = {ov.x, ov.y, ov.z, ov.w};
#pragma unroll
        for (int p = 0; p < 4; ++p) {
            unsigned long long o2 = pack2(orr[p], orr[p]);
            acc[p][0] = fma2(o2, p_lo.x, acc[p][0]);
            acc[p][1] = fma2(o2, p_lo.y, acc[p][1]);
            acc[p][2] = fma2(o2, p_hi.x, acc[p][2]);
            acc[p][3] = fma2(o2, p_hi.y, acc[p][3]);
        }
    }

    // stage to out_s[(p*64+c)][t]
    __syncthreads();
#pragma unroll
    for (int p = 0; p < 4; ++p)
#pragma unroll
        for (int i = 0; i < 4; ++i) {
            float lo, hi;
            unpack2(acc[p][i], lo, hi);
            x_s[(p * 64 + h * 8 + 2 * i) * 32 + t] = lo;
            x_s[(p * 64 + h * 8 + 2 * i + 1) * 32 + t] = hi;
        }
    __syncthreads();

    // coalesced float4 writeback
    for (int i4 = tid; i4 < 2048; i4 += 256) {
        int pc = i4 >> 3;
        int t4 = (i4 & 7) * 4;
        int p = pc >> 6, c = pc & 63;
        float4 v = *(const float4*)(x_s + pc * 32 + t4);
        *(float4*)(out + (size_t)((b * 4 + p) * 64 + c) * HW + pos0 + t4) = v;
    }
}

// ---------------------------------------------------------------------------
extern "C" void kernel_launch(void* const* d_in, const int* in_sizes, int n_in,
                              void* d_out, int out_size) {
    (void)in_sizes; (void)n_in; (void)out_size;
    const float* x_in   = (const float*)d_in[0];
    const float* mask   = (const float*)d_in[1];
    const float* wq     = (const float*)d_in[2];
    const float* wk     = (const float*)d_in[3];
    const float* wv     = (const float*)d_in[4];
    const float* w_proj = (const float*)d_in[5];
    const float* b_proj = (const float*)d_in[6];
    const float* rescale= (const float*)d_in[7];
    const float* dw_w   = (const float*)d_in[8];
    const float* dw_b   = (const float*)d_in[9];
    const float* pw_w   = (const float*)d_in[10];
    const float* pw_b   = (const float*)d_in[11];
    float* out = (float*)d_out;

    cudaFuncSetAttribute(attn_kernel,
                         cudaFuncAttributeMaxDynamicSharedMemorySize,
                         SMEM_FLOATS * sizeof(float));

    mask_kernel2<<<dim3(8, 8, 16), dim3(16, 16)>>>(mask, dw_w, dw_b, pw_w, pw_b);
    attn_kernel<<<dim3(HW / TOK, Bn), 256, SMEM_FLOATS * sizeof(float)>>>(
        x_in, wq, wk, wv, w_proj, b_proj, rescale, out);
}

// round 7
// speedup vs baseline: 2.1413x; 1.0473x over previous
#include <cuda_runtime.h>
#include <cuda_bf16.h>
#include <math.h>

#define Bn 4
#define Pp 4
#define Cc 64
#define NH 8
#define Hh 128
#define Wd 128
#define HW 16384

// scratch (no cudaMalloc allowed)
__device__ float g_mb[16 * HW];                  // mask bias per (b,p,pos)
__device__ float g_qkv[(size_t)262144 * 192];    // [row=(b,pos,p)][q0..63|k|v]

// ---------------------------------------------------------------------------
// helpers
// ---------------------------------------------------------------------------
__device__ __forceinline__ void bsplit(float f, __nv_bfloat16& h, __nv_bfloat16& l) {
    h = __float2bfloat16(f);
    l = __float2bfloat16(f - __bfloat162float(h));
}

__device__ __forceinline__ void mma16816(float* c, const unsigned* a,
                                         unsigned b0, unsigned b1) {
    asm volatile(
        "mma.sync.aligned.m16n8k16.row.col.f32.bf16.bf16.f32 "
        "{%0,%1,%2,%3}, {%4,%5,%6,%7}, {%8,%9}, {%0,%1,%2,%3};"
        : "+f"(c[0]), "+f"(c[1]), "+f"(c[2]), "+f"(c[3])
        : "r"(a[0]), "r"(a[1]), "r"(a[2]), "r"(a[3]), "r"(b0), "r"(b1));
}

// ---------------------------------------------------------------------------
// Kernel 1: mask branch. 16 channels per barrier round.
// dw3x3 -> exact GELU -> dot with column-mean(pw_w) + mean(pw_b)
// ---------------------------------------------------------------------------
__global__ void mask_kernel2(const float* __restrict__ mask,
                             const float* __restrict__ dw_w,
                             const float* __restrict__ dw_b,
                             const float* __restrict__ pw_w,
                             const float* __restrict__ pw_b) {
    __shared__ float tile[16][18][20];
    __shared__ float sdw[Cc][9];
    __shared__ float sdb[Cc];
    __shared__ float swbar[Cc + 1];
    __shared__ float wpart[4][Cc];

    int bp = blockIdx.z;
    int h0 = blockIdx.y * 16, w0 = blockIdx.x * 16;
    int tx = threadIdx.x, ty = threadIdx.y;
    int tid = ty * 16 + tx;

    for (int i = tid; i < Cc * 9; i += 256) sdw[i / 9][i % 9] = dw_w[i];
    for (int i = tid; i < Cc; i += 256) sdb[i] = dw_b[i];
    {
        int c = tid & 63, dg = tid >> 6;
        float s = 0.f;
        for (int d = dg * 16; d < dg * 16 + 16; ++d) s += pw_w[d * Cc + c];
        wpart[dg][c] = s;
    }
    if (tid >= 192) {
        float s = pw_b[tid - 192];
#pragma unroll
        for (int o = 16; o > 0; o >>= 1)
            s += __shfl_down_sync(0xFFFFFFFFu, s, o);
        if (tid == 192) swbar[Cc] = s * (1.0f / Cc);
    }
    __syncthreads();
    if (tid < Cc)
        swbar[tid] = (wpart[0][tid] + wpart[1][tid] + wpart[2][tid] + wpart[3][tid]) * (1.0f / Cc);

    float acc = 0.f;
    const float* base = mask + (size_t)bp * Cc * HW;

    for (int cb = 0; cb < Cc; cb += 16) {
        __syncthreads();
        for (int i = tid; i < 16 * 324; i += 256) {
            int cc = i / 324, r = i % 324;
            int hy = r / 18, wx = r % 18;
            int gh = h0 + hy - 1, gw = w0 + wx - 1;
            float v = 0.f;
            if (gh >= 0 && gh < Hh && gw >= 0 && gw < Wd)
                v = base[(size_t)(cb + cc) * HW + gh * Wd + gw];
            tile[cc][hy][wx] = v;
        }
        __syncthreads();
#pragma unroll
        for (int cc = 0; cc < 16; ++cc) {
            int c = cb + cc;
            float y = sdb[c];
#pragma unroll
            for (int dy = 0; dy < 3; ++dy)
#pragma unroll
                for (int dx = 0; dx < 3; ++dx)
                    y += tile[cc][ty + dy][tx + dx] * sdw[c][dy * 3 + dx];
            float g = 0.5f * y * (1.0f + erff(y * 0.70710678118654752f));
            acc += swbar[c] * g;
        }
    }
    acc += swbar[Cc];
    g_mb[(size_t)bp * HW + (h0 + ty) * Wd + (w0 + tx)] = acc;
}

// ---------------------------------------------------------------------------
// Kernel 2: QKV GEMM via mma.sync bf16 (hi+lo x3 for fp32 accuracy).
// C[262144,192] = X[262144,64] * W^T (W = [wq;wk;wv] each [64 out][64 in]).
// Block: 256 thr, tile M=128 (32 pos x 4 p), N=192, K=64.
// smem (bf16, stride 72): aHi[128*72] aLo[128*72] bHi[192*72] bLo[192*72]
// ---------------------------------------------------------------------------
#define QKV_SMEM_BYTES ((9216 * 2 + 13824 * 2) * 2)

__global__ void __launch_bounds__(256)
qkv_gemm(const float* __restrict__ x_in,
         const float* __restrict__ wq,
         const float* __restrict__ wk,
         const float* __restrict__ wv) {
    extern __shared__ __nv_bfloat16 smb[];
    __nv_bfloat16* aHi = smb;
    __nv_bfloat16* aLo = smb + 9216;
    __nv_bfloat16* bHi = smb + 18432;
    __nv_bfloat16* bLo = smb + 18432 + 13824;

    int tid = threadIdx.x;
    int blk = blockIdx.x;
    int b = blk >> 9;
    int pos0 = (blk & 511) * 32;

    // stage B = [wq|wk|wv] rows n=0..191, cols c=0..63
    for (int i = tid; i < 12288; i += 256) {
        int n = i >> 6, c = i & 63;
        float w = (n < 64) ? wq[n * 64 + c]
                : (n < 128) ? wk[(n - 64) * 64 + c]
                            : wv[(n - 128) * 64 + c];
        __nv_bfloat16 h, l;
        bsplit(w, h, l);
        bHi[n * 72 + c] = h;
        bLo[n * 72 + c] = l;
    }
    // stage A: rows = pos_local*4 + p, cols = c
    for (int i4 = tid; i4 < 2048; i4 += 256) {
        int pc = i4 >> 3;
        int t4 = (i4 & 7) * 4;
        int p = pc >> 6, c = pc & 63;
        float4 xv = *(const float4*)(x_in + (size_t)((b * 4 + p) * 64 + c) * HW + pos0 + t4);
        float xs[4] = {xv.x, xv.y, xv.z, xv.w};
#pragma unroll
        for (int j = 0; j < 4; ++j) {
            int row = (t4 + j) * 4 + p;
            __nv_bfloat16 h, l;
            bsplit(xs[j], h, l);
            aHi[row * 72 + c] = h;
            aLo[row * 72 + c] = l;
        }
    }
    __syncthreads();

    int lane = tid & 31, wid = tid >> 5;
    int gid = lane >> 2, tig = lane & 3;
    int wm = wid & 3, wn = wid >> 2;
    int row0 = wm * 32, col0 = wn * 96;

    float acc[2][12][4];
#pragma unroll
    for (int mt = 0; mt < 2; ++mt)
#pragma unroll
        for (int nb = 0; nb < 12; ++nb)
#pragma unroll
            for (int i = 0; i < 4; ++i) acc[mt][nb][i] = 0.f;

#pragma unroll
    for (int kk = 0; kk < 4; ++kk) {
        unsigned aH[2][4], aL[2][4];
#pragma unroll
        for (int mt = 0; mt < 2; ++mt) {
            const __nv_bfloat16* ab = aHi + (row0 + mt * 16 + gid) * 72 + kk * 16 + 2 * tig;
            aH[mt][0] = *(const unsigned*)(ab);
            aH[mt][1] = *(const unsigned*)(ab + 8 * 72);
            aH[mt][2] = *(const unsigned*)(ab + 8);
            aH[mt][3] = *(const unsigned*)(ab + 8 * 72 + 8);
            const __nv_bfloat16* al = aLo + (row0 + mt * 16 + gid) * 72 + kk * 16 + 2 * tig;
            aL[mt][0] = *(const unsigned*)(al);
            aL[mt][1] = *(const unsigned*)(al + 8 * 72);
            aL[mt][2] = *(const unsigned*)(al + 8);
            aL[mt][3] = *(const unsigned*)(al + 8 * 72 + 8);
        }
#pragma unroll
        for (int nb = 0; nb < 12; ++nb) {
            int n = col0 + nb * 8 + gid;
            const __nv_bfloat16* bh = bHi + n * 72 + kk * 16 + 2 * tig;
            unsigned bh0 = *(const unsigned*)(bh);
            unsigned bh1 = *(const unsigned*)(bh + 8);
            const __nv_bfloat16* bl = bLo + n * 72 + kk * 16 + 2 * tig;
            unsigned bl0 = *(const unsigned*)(bl);
            unsigned bl1 = *(const unsigned*)(bl + 8);
#pragma unroll
            for (int mt = 0; mt < 2; ++mt) {
                mma16816(acc[mt][nb], aH[mt], bh0, bh1);
                mma16816(acc[mt][nb], aH[mt], bl0, bl1);
                mma16816(acc[mt][nb], aL[mt], bh0, bh1);
            }
        }
    }

    // epilogue -> g_qkv fp32
    size_t rowg = ((size_t)b * HW + pos0) * 4;
#pragma unroll
    for (int mt = 0; mt < 2; ++mt)
#pragma unroll
        for (int nb = 0; nb < 12; ++nb) {
            int row = row0 + mt * 16 + gid;
            int col = col0 + nb * 8 + 2 * tig;
            float* dst = g_qkv + (rowg + row) * 192 + col;
            *(float2*)dst = make_float2(acc[mt][nb][0], acc[mt][nb][1]);
            *(float2*)(dst + (size_t)8 * 192) = make_float2(acc[mt][nb][2], acc[mt][nb][3]);
        }
}

// ---------------------------------------------------------------------------
// Kernel 3: per-token attention mid-section + projection GEMM + writeback.
// Block: 256 thr = 32 tokens x 8 heads; 2 CTAs/SM.
// smem: aHi[128*72] aLo[128*72] bHi[64*72] bLo[64*72] (bf16)
//       + mb_s[128] sb[64] sr[8] (f32). out_s (f32[8192]) overlays aHi/aLo.
// ---------------------------------------------------------------------------
#define ATTN_SMEM_BYTES (27648 * 2 + 800)

__global__ void __launch_bounds__(256, 2)
attn2(const float* __restrict__ wp,
      const float* __restrict__ b_proj,
      const float* __restrict__ rescale,
      float* __restrict__ out) {
    extern __shared__ __nv_bfloat16 smb[];
    __nv_bfloat16* aHi = smb;
    __nv_bfloat16* aLo = smb + 9216;
    __nv_bfloat16* bHi = smb + 18432;
    __nv_bfloat16* bLo = smb + 23040;
    float* fx   = (float*)(smb + 27648);
    float* mb_s = fx;
    float* sb   = fx + 128;
    float* sr   = fx + 192;
    float* out_s = (float*)smb;   // overlays A after GEMM

    int tid = threadIdx.x;
    int b = blockIdx.y;
    int pos0 = blockIdx.x * 32;

    // stage projection weights
    for (int i = tid; i < 4096; i += 256) {
        int n = i >> 6, c = i & 63;
        __nv_bfloat16 h, l;
        bsplit(wp[n * 64 + c], h, l);
        bHi[n * 72 + c] = h;
        bLo[n * 72 + c] = l;
    }
    if (tid < 128) {
        int p = tid >> 5, t = tid & 31;
        mb_s[t * 4 + p] = g_mb[(size_t)(b * 4 + p) * HW + pos0 + t];
    }
    if (tid < 64) sb[tid] = b_proj[tid];
    if (tid < 8) sr[tid] = rescale[tid];
    __syncthreads();

    const int t = tid >> 3, h = tid & 7;
    size_t rowg = ((size_t)b * HW + pos0 + t) * 4;

    // ---- load q,k ; normalize ; scores ; softmax ----
    float q[4][8], k[4][8];
#pragma unroll
    for (int p = 0; p < 4; ++p) {
        const float* src = g_qkv + (rowg + p) * 192 + h * 8;
        float4 a0 = *(const float4*)(src);
        float4 a1 = *(const float4*)(src + 4);
        q[p][0] = a0.x; q[p][1] = a0.y; q[p][2] = a0.z; q[p][3] = a0.w;
        q[p][4] = a1.x; q[p][5] = a1.y; q[p][6] = a1.z; q[p][7] = a1.w;
        float4 b0 = *(const float4*)(src + 64);
        float4 b1 = *(const float4*)(src + 68);
        k[p][0] = b0.x; k[p][1] = b0.y; k[p][2] = b0.z; k[p][3] = b0.w;
        k[p][4] = b1.x; k[p][5] = b1.y; k[p][6] = b1.z; k[p][7] = b1.w;
    }
#pragma unroll
    for (int p = 0; p < 4; ++p) {
        float sq = 0.f, sk = 0.f;
#pragma unroll
        for (int j = 0; j < 8; ++j) { sq += q[p][j] * q[p][j]; sk += k[p][j] * k[p][j]; }
        float iq = 1.0f / fmaxf(sqrtf(sq), 1e-12f);
        float ik = 1.0f / fmaxf(sqrtf(sk), 1e-12f);
#pragma unroll
        for (int j = 0; j < 8; ++j) { q[p][j] *= iq; k[p][j] *= ik; }
    }
    float att[4][4];
    {
        float rh = sr[h];
        float mbl[4];
#pragma unroll
        for (int p = 0; p < 4; ++p) mbl[p] = mb_s[t * 4 + p];
#pragma unroll
        for (int p = 0; p < 4; ++p) {
#pragma unroll
            for (int pq = 0; pq < 4; ++pq) {
                float d = 0.f;
#pragma unroll
                for (int j = 0; j < 8; ++j) d += q[p][j] * k[pq][j];
                att[p][pq] = d * rh + (mbl[pq] - mbl[p]);
            }
            float mx = fmaxf(fmaxf(att[p][0], att[p][1]), fmaxf(att[p][2], att[p][3]));
            float s = 0.f;
#pragma unroll
            for (int pq = 0; pq < 4; ++pq) { att[p][pq] = __expf(att[p][pq] - mx); s += att[p][pq]; }
            float inv = 1.0f / s;
#pragma unroll
            for (int pq = 0; pq < 4; ++pq) att[p][pq] *= inv;
        }
    }

    // ---- o = att @ v ; store to A (bf16 hi/lo) ----
    float v[4][8];
#pragma unroll
    for (int p = 0; p < 4; ++p) {
        const float* src = g_qkv + (rowg + p) * 192 + 128 + h * 8;
        float4 a0 = *(const float4*)(src);
        float4 a1 = *(const float4*)(src + 4);
        v[p][0] = a0.x; v[p][1] = a0.y; v[p][2] = a0.z; v[p][3] = a0.w;
        v[p][4] = a1.x; v[p][5] = a1.y; v[p][6] = a1.z; v[p][7] = a1.w;
    }
#pragma unroll
    for (int p = 0; p < 4; ++p) {
        int row = t * 4 + p;
#pragma unroll
        for (int j = 0; j < 8; ++j) {
            float o = att[p][0] * v[0][j] + att[p][1] * v[1][j] +
                      att[p][2] * v[2][j] + att[p][3] * v[3][j];
            __nv_bfloat16 hh, ll;
            bsplit(o, hh, ll);
            aHi[row * 72 + h * 8 + j] = hh;
            aLo[row * 72 + h * 8 + j] = ll;
        }
    }
    __syncthreads();

    // ---- projection GEMM: [128 x 64] = A[128 x 64] * wp^T ----
    int lane = tid & 31, wid = tid >> 5;
    int gid = lane >> 2, tig = lane & 3;
    int wm = wid & 3, wn = wid >> 2;
    int row0 = wm * 32, col0 = wn * 32;

    float acc[2][4][4];
#pragma unroll
    for (int mt = 0; mt < 2; ++mt)
#pragma unroll
        for (int nb = 0; nb < 4; ++nb)
#pragma unroll
            for (int i = 0; i < 4; ++i) acc[mt][nb][i] = 0.f;

#pragma unroll
    for (int kk = 0; kk < 4; ++kk) {
        unsigned aH[2][4], aL[2][4];
#pragma unroll
        for (int mt = 0; mt < 2; ++mt) {
            const __nv_bfloat16* ab = aHi + (row0 + mt * 16 + gid) * 72 + kk * 16 + 2 * tig;
            aH[mt][0] = *(const unsigned*)(ab);
            aH[mt][1] = *(const unsigned*)(ab + 8 * 72);
            aH[mt][2] = *(const unsigned*)(ab + 8);
            aH[mt][3] = *(const unsigned*)(ab + 8 * 72 + 8);
            const __nv_bfloat16* al = aLo + (row0 + mt * 16 + gid) * 72 + kk * 16 + 2 * tig;
            aL[mt][0] = *(const unsigned*)(al);
            aL[mt][1] = *(const unsigned*)(al + 8 * 72);
            aL[mt][2] = *(const unsigned*)(al + 8);
            aL[mt][3] = *(const unsigned*)(al + 8 * 72 + 8);
        }
#pragma unroll
        for (int nb = 0; nb < 4; ++nb) {
            int n = col0 + nb * 8 + gid;
            const __nv_bfloat16* bh = bHi + n * 72 + kk * 16 + 2 * tig;
            unsigned bh0 = *(const unsigned*)(bh);
            unsigned bh1 = *(const unsigned*)(bh + 8);
            const __nv_bfloat16* bl = bLo + n * 72 + kk * 16 + 2 * tig;
            unsigned bl0 = *(const unsigned*)(bl);
            unsigned bl1 = *(const unsigned*)(bl + 8);
#pragma unroll
            for (int mt = 0; mt < 2; ++mt) {
                mma16816(acc[mt][nb], aH[mt], bh0, bh1);
                mma16816(acc[mt][nb], aH[mt], bl0, bl1);
                mma16816(acc[mt][nb], aL[mt], bh0, bh1);
            }
        }
    }
    __syncthreads();   // A dead; reuse as out_s

    // ---- acc -> out_s[(p*64+c)*32 + t] with bias ----
#pragma unroll
    for (int mt = 0; mt < 2; ++mt)
#pragma unroll
        for (int nb = 0; nb < 4; ++nb) {
            int row = row0 + mt * 16 + gid;
            int col = col0 + nb * 8 + 2 * tig;
            int tt = row >> 2, p = row & 3;
            out_s[(p * 64 + col) * 32 + tt]     = acc[mt][nb][0] + sb[col];
            out_s[(p * 64 + col + 1) * 32 + tt] = acc[mt][nb][1] + sb[col + 1];
            out_s[(p * 64 + col) * 32 + tt + 2]     = acc[mt][nb][2] + sb[col];
            out_s[(p * 64 + col + 1) * 32 + tt + 2] = acc[mt][nb][3] + sb[col + 1];
        }
    __syncthreads();

    // ---- coalesced writeback ----
    for (int i4 = tid; i4 < 2048; i4 += 256) {
        int pc = i4 >> 3;
        int t4 = (i4 & 7) * 4;
        int p = pc >> 6, c = pc & 63;
        float4 vv = *(const float4*)(out_s + pc * 32 + t4);
        *(float4*)(out + (size_t)((b * 4 + p) * 64 + c) * HW + pos0 + t4) = vv;
    }
}

// ---------------------------------------------------------------------------
extern "C" void kernel_launch(void* const* d_in, const int* in_sizes, int n_in,
                              void* d_out, int out_size) {
    (void)in_sizes; (void)n_in; (void)out_size;
    const float* x_in   = (const float*)d_in[0];
    const float* mask   = (const float*)d_in[1];
    const float* wq     = (const float*)d_in[2];
    const float* wk     = (const float*)d_in[3];
    const float* wv     = (const float*)d_in[4];
    const float* w_proj = (const float*)d_in[5];
    const float* b_proj = (const float*)d_in[6];
    const float* rescale= (const float*)d_in[7];
    const float* dw_w   = (const float*)d_in[8];
    const float* dw_b   = (const float*)d_in[9];
    const float* pw_w   = (const float*)d_in[10];
    const float* pw_b   = (const float*)d_in[11];
    float* out = (float*)d_out;

    cudaFuncSetAttribute(qkv_gemm, cudaFuncAttributeMaxDynamicSharedMemorySize,
                         QKV_SMEM_BYTES);
    cudaFuncSetAttribute(attn2, cudaFuncAttributeMaxDynamicSharedMemorySize,
                         ATTN_SMEM_BYTES);

    mask_kernel2<<<dim3(8, 8, 16), dim3(16, 16)>>>(mask, dw_w, dw_b, pw_w, pw_b);
    qkv_gemm<<<2048, 256, QKV_SMEM_BYTES>>>(x_in, wq, wk, wv);
    attn2<<<dim3(512, Bn), 256, ATTN_SMEM_BYTES>>>(w_proj, b_proj, rescale, out);
}